// round 1
// baseline (speedup 1.0000x reference)
#include <cuda_runtime.h>
#include <cstdint>

#define BATCH 2
#define MPTS  5000
#define CH    128
#define KSPP  50
#define NSAMP 2000
#define KNN   1000
#define EPSF  1e-8f

// 80 MB scratch for one branch's d2-partial (bb[m] - 2*dot), reused across branches.
__device__ __align__(16) float g_d2[(size_t)BATCH * NSAMP * MPTS];
// squared norms of feat rows: [branch][b][m]
__device__ __align__(16) float g_bb[2 * BATCH * MPTS];
// accumulators: 0=dist sim sum, 1=ortho sse, 2=bij sse, 3=res sse
__device__ float g_acc[4];

// ---------- packed f32x2 helpers (Blackwell FFMA2) ----------
__device__ __forceinline__ unsigned long long pack2(float x, float y) {
    unsigned long long r;
    asm("mov.b64 %0, {%1, %2};" : "=l"(r) : "f"(x), "f"(y));
    return r;
}
__device__ __forceinline__ void fma2(unsigned long long& d, unsigned long long a,
                                     unsigned long long b) {
    asm("fma.rn.f32x2 %0, %1, %2, %0;" : "+l"(d) : "l"(a), "l"(b));
}
__device__ __forceinline__ void unpack2(unsigned long long v, float& lo, float& hi) {
    asm("mov.b64 {%0, %1}, %2;" : "=f"(lo), "=f"(hi) : "l"(v));
}

__device__ __forceinline__ float warp_sum(float v) {
    #pragma unroll
    for (int o = 16; o; o >>= 1) v += __shfl_xor_sync(0xffffffffu, v, o);
    return v;
}

// ---------- kernel 1: row norms for both feats + zero accumulators ----------
__global__ void init_norms(const float* __restrict__ f1, const float* __restrict__ f2) {
    if (blockIdx.x == 0 && threadIdx.x < 4) g_acc[threadIdx.x] = 0.f;
    int w = blockIdx.x * 8 + (threadIdx.x >> 5);
    int lane = threadIdx.x & 31;
    if (w >= 2 * BATCH * MPTS) return;
    int branch = w / (BATCH * MPTS);
    int bm = w % (BATCH * MPTS);
    const float* f = (branch ? f2 : f1) + (size_t)bm * CH + lane * 4;
    float4 v = *reinterpret_cast<const float4*>(f);
    float ss = v.x * v.x + v.y * v.y + v.z * v.z + v.w * v.w;
    ss = warp_sum(ss);
    if (lane == 0) g_bb[branch * (BATCH * MPTS) + bm] = ss;
}

// ---------- kernel 2: d2-partial GEMM: g_d2[b][n][m] = bb[m] - 2 * <f1[n], feat[m]> ----------
// 128x128 tile, K=128, BK=8, 256 threads, 8x8 per thread via fma.rn.f32x2 (FFMA2).
__global__ __launch_bounds__(256, 2) void gemm_d2(const float* __restrict__ feat,
                                                  const int* __restrict__ ridx,
                                                  int branch) {
    __shared__ __align__(16) float As[8][128];
    __shared__ __align__(16) float Bs[8][128];
    int tid = threadIdx.x;
    int bx = blockIdx.x, by = blockIdx.y, bz = blockIdx.z;
    const float* fb = feat + (size_t)bz * MPTS * CH;
    const float* bbp = g_bb + branch * (BATCH * MPTS) + bz * MPTS;

    // global->smem load assignment: thread loads one float4 of A and one of B per k-block
    int lrow = tid >> 1;
    int lk4  = (tid & 1) * 4;
    int an = by * 128 + lrow;
    bool aval = an < NSAMP;
    const float* aptr = fb + (size_t)(aval ? ridx[an] : 0) * CH + lk4;
    int bm = bx * 128 + lrow;
    bool bval = bm < MPTS;
    const float* bptr = fb + (size_t)(bval ? bm : 0) * CH + lk4;

    int tx = tid & 15, ty = tid >> 4;
    int tx4 = tx * 4, ty4 = ty * 4;

    unsigned long long acc[8][4];
    #pragma unroll
    for (int i = 0; i < 8; i++)
        #pragma unroll
        for (int j = 0; j < 4; j++) acc[i][j] = 0ull;

    for (int kb = 0; kb < 16; ++kb) {
        float4 av = aval ? *reinterpret_cast<const float4*>(aptr + kb * 8)
                         : make_float4(0.f, 0.f, 0.f, 0.f);
        float4 bv = bval ? *reinterpret_cast<const float4*>(bptr + kb * 8)
                         : make_float4(0.f, 0.f, 0.f, 0.f);
        __syncthreads();   // previous iteration's compute done before overwrite
        As[lk4 + 0][lrow] = av.x; As[lk4 + 1][lrow] = av.y;
        As[lk4 + 2][lrow] = av.z; As[lk4 + 3][lrow] = av.w;
        Bs[lk4 + 0][lrow] = bv.x; Bs[lk4 + 1][lrow] = bv.y;
        Bs[lk4 + 2][lrow] = bv.z; Bs[lk4 + 3][lrow] = bv.w;
        __syncthreads();
        #pragma unroll
        for (int kk = 0; kk < 8; kk++) {
            float4 a0 = *reinterpret_cast<const float4*>(&As[kk][ty4]);
            float4 a1 = *reinterpret_cast<const float4*>(&As[kk][64 + ty4]);
            float4 b0 = *reinterpret_cast<const float4*>(&Bs[kk][tx4]);
            float4 b1 = *reinterpret_cast<const float4*>(&Bs[kk][64 + tx4]);
            unsigned long long bp[4] = {pack2(b0.x, b0.y), pack2(b0.z, b0.w),
                                        pack2(b1.x, b1.y), pack2(b1.z, b1.w)};
            float ar[8] = {a0.x, a0.y, a0.z, a0.w, a1.x, a1.y, a1.z, a1.w};
            #pragma unroll
            for (int i = 0; i < 8; i++) {
                unsigned long long ad = pack2(ar[i], ar[i]);
                #pragma unroll
                for (int j = 0; j < 4; j++) fma2(acc[i][j], ad, bp[j]);
            }
        }
    }

    // epilogue: d2_partial = bb[m] - 2*dot, vectorized stores
    int n0 = by * 128 + ty4;
    int m0 = bx * 128 + tx4;
    int m1 = m0 + 64;
    float4 bb0 = make_float4(0.f, 0.f, 0.f, 0.f), bb1 = bb0;
    if (m0 < MPTS) bb0 = *reinterpret_cast<const float4*>(bbp + m0);
    if (m1 < MPTS) bb1 = *reinterpret_cast<const float4*>(bbp + m1);
    #pragma unroll
    for (int i = 0; i < 8; i++) {
        int n = (i < 4) ? (n0 + i) : (n0 + 64 + i - 4);
        if (n >= NSAMP) continue;
        float* orow = g_d2 + ((size_t)bz * NSAMP + n) * MPTS;
        float d[8];
        #pragma unroll
        for (int j = 0; j < 4; j++) { unpack2(acc[i][j], d[j * 2], d[j * 2 + 1]); }
        if (m0 < MPTS) {
            float4 o;
            o.x = fmaf(-2.f, d[0], bb0.x); o.y = fmaf(-2.f, d[1], bb0.y);
            o.z = fmaf(-2.f, d[2], bb0.z); o.w = fmaf(-2.f, d[3], bb0.w);
            *reinterpret_cast<float4*>(orow + m0) = o;
        }
        if (m1 < MPTS) {
            float4 o;
            o.x = fmaf(-2.f, d[4], bb1.x); o.y = fmaf(-2.f, d[5], bb1.y);
            o.z = fmaf(-2.f, d[6], bb1.z); o.w = fmaf(-2.f, d[7], bb1.w);
            *reinterpret_cast<float4*>(orow + m1) = o;
        }
    }
}

// ---------- kernel 3: per-row exact k=1000 radix select + cosine reduction ----------
__global__ __launch_bounds__(256) void select_reduce(const float* __restrict__ dist,
                                                     const int* __restrict__ ridx,
                                                     int branch) {
    __shared__ __align__(16) unsigned int keys[MPTS];
    __shared__ unsigned int hist[256];
    __shared__ unsigned int sh_P;
    __shared__ int sh_r;
    __shared__ int sh_eq;
    __shared__ float red[96];

    int tid = threadIdx.x;
    int b = blockIdx.x / NSAMP;
    int n = blockIdx.x % NSAMP;
    int col = ridx[n];
    float aa = g_bb[branch * (BATCH * MPTS) + b * MPTS + col];
    const float* rowp = g_d2 + (size_t)blockIdx.x * MPTS;

    // load row, add aa, clamp to >= 0 (bit pattern then orders correctly)
    for (int q = tid; q < MPTS / 4; q += 256) {
        float4 v = reinterpret_cast<const float4*>(rowp)[q];
        uint4 k;
        k.x = __float_as_uint(fmaxf(v.x + aa, 0.f));
        k.y = __float_as_uint(fmaxf(v.y + aa, 0.f));
        k.z = __float_as_uint(fmaxf(v.z + aa, 0.f));
        k.w = __float_as_uint(fmaxf(v.w + aa, 0.f));
        reinterpret_cast<uint4*>(keys)[q] = k;
    }
    if (tid == 0) { sh_P = 0; sh_r = KNN; sh_eq = 0; }
    __syncthreads();

    // 4-pass MSD radix select for the exact 1000th-smallest key
    #pragma unroll
    for (int pass = 0; pass < 4; ++pass) {
        int shift = 24 - 8 * pass;
        hist[tid] = 0;
        __syncthreads();
        unsigned int P = sh_P;
        unsigned int pmask = (pass == 0) ? 0u : (0xFFFFFFFFu << ((shift + 8) & 31));
        for (int i = tid; i < MPTS; i += 256) {
            unsigned int k = keys[i];
            if ((k & pmask) == P) atomicAdd(&hist[(k >> shift) & 255], 1u);
        }
        __syncthreads();
        if (tid == 0) {
            unsigned int r = (unsigned int)sh_r, cum = 0;
            int t = 0;
            for (; t < 256; ++t) {
                unsigned int c = hist[t];
                if (cum + c >= r) break;
                cum += c;
            }
            sh_P = P | ((unsigned int)t << shift);
            sh_r = (int)(r - cum);
        }
        __syncthreads();
    }
    unsigned int T = sh_P;   // key of the 1000th smallest
    int need_eq = sh_r;      // how many ties at T to include

    const float* dcol = dist + (size_t)b * MPTS * MPTS + col;
    float num = 0.f, s1 = 0.f, s2 = 0.f;
    for (int i = tid; i < MPTS; i += 256) {
        unsigned int k = keys[i];
        bool take = (k < T);
        if (!take && k == T) take = (atomicAdd(&sh_eq, 1) < need_eq);
        if (take) {
            float dr = sqrtf(fmaxf(__uint_as_float(k), 1e-12f));
            float df = __ldg(dcol + (size_t)i * MPTS);
            num = fmaf(dr, df, num);
            s1  = fmaf(dr, dr, s1);
            s2  = fmaf(df, df, s2);
        }
    }
    num = warp_sum(num); s1 = warp_sum(s1); s2 = warp_sum(s2);
    int w = tid >> 5, lane = tid & 31;
    if (lane == 0) { red[w] = num; red[32 + w] = s1; red[64 + w] = s2; }
    __syncthreads();
    if (tid == 0) {
        float N = 0.f, S1 = 0.f, S2 = 0.f;
        #pragma unroll
        for (int i = 0; i < 8; i++) { N += red[i]; S1 += red[32 + i]; S2 += red[64 + i]; }
        float den = fmaxf(sqrtf(S1), EPSF) * fmaxf(sqrtf(S2), EPSF);
        float sim = 1.f - fabsf(N / den);
        atomicAdd(&g_acc[0], sim);
    }
}

// ---------- kernel 4: ortho / bij / res losses on the 50x50 matrices ----------
__global__ void small_losses(const float* __restrict__ A0, const float* __restrict__ A1,
                             const float* __restrict__ A2, const float* __restrict__ A3) {
    __shared__ float shA[KSPP * KSPP];
    __shared__ float shB[KSPP * KSPP];
    __shared__ float red[8];
    int t = blockIdx.x, b = blockIdx.y, tid = threadIdx.x;
    const float* mats[4] = {A0, A1, A2, A3};
    size_t off = (size_t)b * KSPP * KSPP;
    float local = 0.f;
    if (t == 6) {
        for (int e = tid; e < KSPP * KSPP; e += 256) {
            float d1 = A0[off + e] - A2[off + e];
            float d2 = A1[off + e] - A3[off + e];
            local += d1 * d1 + d2 * d2;
        }
    } else {
        int ai, bi; bool tb;
        switch (t) {
            case 0: ai = 0; bi = 0; tb = true;  break;
            case 1: ai = 1; bi = 1; tb = true;  break;
            case 2: ai = 2; bi = 2; tb = true;  break;
            case 3: ai = 3; bi = 3; tb = true;  break;
            case 4: ai = 0; bi = 1; tb = false; break;
            default: ai = 1; bi = 0; tb = false; break;
        }
        for (int e = tid; e < KSPP * KSPP; e += 256) {
            shA[e] = mats[ai][off + e];
            shB[e] = mats[bi][off + e];
        }
        __syncthreads();
        for (int e = tid; e < KSPP * KSPP; e += 256) {
            int i = e / KSPP, j = e % KSPP;
            float dot = 0.f;
            if (tb) {
                for (int k = 0; k < KSPP; k++) dot = fmaf(shA[i * KSPP + k], shB[j * KSPP + k], dot);
            } else {
                for (int k = 0; k < KSPP; k++) dot = fmaf(shA[i * KSPP + k], shB[k * KSPP + j], dot);
            }
            float diff = dot - (i == j ? 1.f : 0.f);
            local += diff * diff;
        }
    }
    local = warp_sum(local);
    if ((tid & 31) == 0) red[tid >> 5] = local;
    __syncthreads();
    if (tid == 0) {
        float s = 0.f;
        #pragma unroll
        for (int i = 0; i < 8; i++) s += red[i];
        int slot = (t < 4) ? 1 : ((t < 6) ? 2 : 3);
        atomicAdd(&g_acc[slot], s);
    }
}

// ---------- kernel 5: combine ----------
__global__ void finalize(float* __restrict__ out) {
    float dist  = g_acc[0] * 0.5f;
    float ortho = g_acc[1] / (float)BATCH * 0.5f;
    float bij   = g_acc[2] / (float)BATCH;
    float res   = g_acc[3] / (float)BATCH;
    out[0] = dist + ortho + bij + res;
    out[1] = ortho;
    out[2] = bij;
    out[3] = res;
    out[4] = dist;
}

extern "C" void kernel_launch(void* const* d_in, const int* in_sizes, int n_in,
                              void* d_out, int out_size) {
    const float* C12   = (const float*)d_in[0];
    const float* C21   = (const float*)d_in[1];
    const float* C12n  = (const float*)d_in[2];
    const float* C21n  = (const float*)d_in[3];
    const float* feat1 = (const float*)d_in[4];
    const float* feat2 = (const float*)d_in[5];
    // d_in[6], d_in[7] (evecs_trans) unused by the reference
    const float* dist1 = (const float*)d_in[8];
    const float* dist2 = (const float*)d_in[9];
    const int*   ri1   = (const int*)d_in[10];
    const int*   ri2   = (const int*)d_in[11];
    float* out = (float*)d_out;

    init_norms<<<2500, 256>>>(feat1, feat2);

    dim3 ggrid((MPTS + 127) / 128, (NSAMP + 127) / 128, BATCH);  // 40 x 16 x 2
    gemm_d2<<<ggrid, 256>>>(feat1, ri1, 0);
    select_reduce<<<BATCH * NSAMP, 256>>>(dist1, ri1, 0);
    gemm_d2<<<ggrid, 256>>>(feat2, ri2, 1);
    select_reduce<<<BATCH * NSAMP, 256>>>(dist2, ri2, 1);

    small_losses<<<dim3(7, BATCH), 256>>>(C12, C21, C12n, C21n);
    finalize<<<1, 1>>>(out);
}